// round 2
// baseline (speedup 1.0000x reference)
#include <cuda_runtime.h>
#include <cstdint>

#define SEQ 4096
#define HID 256
#define EMB 256

// ---------------------------------------------------------------------------
// Scratch: x_proj[t][j] (4096 x 256 fp32 = 4 MB). Device global (no alloc).
// ---------------------------------------------------------------------------
__device__ float g_xproj[SEQ * HID];

// ---------------------------------------------------------------------------
// Phase 1: x_proj = embedding[tokens] @ wx_w.T + wx_b   (unchanged — ~1% of time)
// ---------------------------------------------------------------------------
#define TOK_PER_BLK 16

__global__ __launch_bounds__(256) void xproj_kernel(
    const int* __restrict__ tokens,
    const float* __restrict__ embedding,
    const float* __restrict__ wx_w,
    const float* __restrict__ wx_b)
{
    __shared__ float emb_sm[TOK_PER_BLK * EMB];
    const int tid = threadIdx.x;
    const int t0  = blockIdx.x * TOK_PER_BLK;

    #pragma unroll
    for (int i = 0; i < TOK_PER_BLK; i++) {
        long tok = (long)tokens[t0 + i];
        emb_sm[i * EMB + tid] = embedding[tok * (long)EMB + tid];
    }
    __syncthreads();

    float acc[TOK_PER_BLK];
    #pragma unroll
    for (int i = 0; i < TOK_PER_BLK; i++) acc[i] = 0.f;

    const float4* wrow = reinterpret_cast<const float4*>(wx_w + tid * EMB);
    #pragma unroll 4
    for (int k4 = 0; k4 < EMB / 4; k4++) {
        float4 w = wrow[k4];
        #pragma unroll
        for (int i = 0; i < TOK_PER_BLK; i++) {
            float4 e = *reinterpret_cast<const float4*>(&emb_sm[i * EMB + 4 * k4]);
            acc[i] += w.x * e.x + w.y * e.y + w.z * e.z + w.w * e.w;
        }
    }

    const float b = wx_b[tid];
    #pragma unroll
    for (int i = 0; i < TOK_PER_BLK; i++)
        g_xproj[(t0 + i) * HID + tid] = acc[i] + b;
}

// ---------------------------------------------------------------------------
// Phase 2: serial recurrence, 2-CTA cluster, mbarrier pipeline.
//
// Thread map (512 thr/CTA): o = tid>>2 (128 outputs/CTA), seg = tid&3.
// Each thread covers 64 k's: 32 "local" (k in own CTA's output range, produced
// locally each step) + 32 "remote" (delivered by peer's cp.async.bulk).
// Weights register-resident as packed f32x2; dot via fma.rn.f32x2; 4-way
// partials reduced with 2 warp shuffles (lanes seg=0..3 adjacent).
//
// Per-step protocol (consume hbuf[cur], cur = t&1):
//   phaseA (local half)                      // ready since last __syncthreads
//   wait bar[cur] parity                     // peer's bulk delivered remote half
//   tid0: re-arm bar[cur] (expect 512B) for step t+2
//   phaseB (remote half); shuffle-reduce; writer: sigmoid -> st hbuf[nxt] local
//   __syncthreads()                          // all reads of hbuf[cur] done;
//                                            // local half of hbuf[nxt] published
//   tid0: fence.proxy.async; cp.async.bulk 512B (our outputs) -> peer hbuf[nxt],
//         complete_tx on peer bar[nxt]
//
// Safety: re-arm of bar[b] (tid0, right after its wait) is program-ordered
// before tid0's __syncthreads, which gates our bulk for step t+1, which gates
// the peer's wait(t+1), which gates any bulk targeting bar[b] at step t+2.
// Buffer reuse: peer writes into hbuf[cur_t] only at step t+1, gated (via its
// wait on our step-t bulk, issued after our __syncthreads) on ALL our threads
// having finished reading hbuf[cur_t].
// ---------------------------------------------------------------------------
#define NCTA 2
#define THREADS2 512
#define OUT_PER_CTA 128
#define KHALF 128
#define KSEG 32          // k's per thread per half
#define HALF_BYTES 512   // 128 floats

__device__ __forceinline__ uint32_t smem_u32(const void* p) {
    uint32_t a;
    asm("{ .reg .u64 t; cvta.to.shared.u64 t, %1; cvt.u32.u64 %0, t; }"
        : "=r"(a) : "l"(p));
    return a;
}
__device__ __forceinline__ uint32_t mapa_peer(uint32_t a, uint32_t rank) {
    uint32_t r;
    asm("mapa.shared::cluster.u32 %0, %1, %2;" : "=r"(r) : "r"(a), "r"(rank));
    return r;
}
__device__ __forceinline__ void fma2(unsigned long long& acc,
                                     unsigned long long a, unsigned long long b) {
    asm("fma.rn.f32x2 %0, %1, %2, %0;" : "+l"(acc) : "l"(a), "l"(b));
}
__device__ __forceinline__ unsigned long long pack2(float x, float y) {
    unsigned long long v;
    asm("mov.b64 %0, {%1, %2};" : "=l"(v) : "f"(x), "f"(y));
    return v;
}
__device__ __forceinline__ void unpack2(unsigned long long v, float& x, float& y) {
    asm("mov.b64 {%0, %1}, %2;" : "=f"(x), "=f"(y) : "l"(v));
}
__device__ __forceinline__ void mbar_init(uint32_t addr, uint32_t cnt) {
    asm volatile("mbarrier.init.shared.b64 [%0], %1;" :: "r"(addr), "r"(cnt) : "memory");
}
__device__ __forceinline__ void mbar_expect(uint32_t addr, uint32_t bytes) {
    asm volatile("mbarrier.arrive.expect_tx.shared.b64 _, [%0], %1;"
                 :: "r"(addr), "r"(bytes) : "memory");
}
__device__ __forceinline__ void mbar_wait(uint32_t addr, uint32_t parity) {
    asm volatile(
        "{\n\t"
        ".reg .pred P;\n\t"
        "WAIT_%=:\n\t"
        "mbarrier.try_wait.parity.acquire.cta.shared::cta.b64 P, [%0], %1, 0x989680;\n\t"
        "@P bra.uni DONE_%=;\n\t"
        "bra.uni WAIT_%=;\n\t"
        "DONE_%=:\n\t"
        "}"
        :: "r"(addr), "r"(parity) : "memory");
}
__device__ __forceinline__ void bulk_s2s(uint32_t dst_remote, uint32_t src_local,
                                         uint32_t bytes, uint32_t remote_bar) {
    asm volatile(
        "cp.async.bulk.shared::cluster.shared::cta.mbarrier::complete_tx::bytes "
        "[%0], [%1], %2, [%3];"
        :: "r"(dst_remote), "r"(src_local), "r"(bytes), "r"(remote_bar) : "memory");
}

__global__ __launch_bounds__(THREADS2, 1) __cluster_dims__(NCTA, 1, 1)
void rnn_kernel(const float* __restrict__ wh_w,
                const float* __restrict__ wh_b,
                float* __restrict__ out)
{
    __shared__ __align__(16) float hbuf[2][HID];
    __shared__ __align__(8)  unsigned long long mbar[2];

    const int tid = threadIdx.x;
    uint32_t rank; asm("mov.u32 %0, %%cluster_ctarank;" : "=r"(rank));
    const uint32_t peer = rank ^ 1u;

    const int o      = tid >> 2;
    const int seg    = tid & 3;
    const int oglob  = (int)rank * OUT_PER_CTA + o;
    const bool writer = (seg == 0);

    const int kL0 = (int)rank * KHALF + seg * KSEG;   // local half
    const int kR0 = (int)peer * KHALF + seg * KSEG;   // remote half

    // Register-resident packed weights
    unsigned long long wl[KSEG / 2], wr[KSEG / 2];
    {
        const float* rowL = wh_w + oglob * HID + kL0;
        const float* rowR = wh_w + oglob * HID + kR0;
        #pragma unroll
        for (int i = 0; i < KSEG / 2; i++) {
            wl[i] = pack2(rowL[2 * i], rowL[2 * i + 1]);
            wr[i] = pack2(rowR[2 * i], rowR[2 * i + 1]);
        }
    }

    // Addresses
    const uint32_t h_base  = smem_u32(&hbuf[0][0]);
    const uint32_t b_addr0 = smem_u32(&mbar[0]);
    const uint32_t b_addr1 = smem_u32(&mbar[1]);
    const uint32_t rh_base = mapa_peer(h_base, peer);
    const uint32_t rb0     = mapa_peer(b_addr0, peer);
    const uint32_t rb1     = mapa_peer(b_addr1, peer);

    // Init barriers + pre-arm both phases (one arrival + 512B each)
    if (tid == 0) {
        mbar_init(b_addr0, 1);
        mbar_init(b_addr1, 1);
        mbar_expect(b_addr0, HALF_BYTES);
        mbar_expect(b_addr1, HALF_BYTES);
    }
    __syncthreads();
    asm volatile("barrier.cluster.arrive.aligned;" ::: "memory");
    asm volatile("barrier.cluster.wait.aligned;"   ::: "memory");

    // Step 0 special case: h0 = 0  ->  h1 = sigmoid(xp[0] + b), goes to hbuf[1]
    float bias = 0.f, xp_cur = 0.f, hn = 0.f;
    if (writer) {
        bias = wh_b[oglob];
        float z = g_xproj[oglob] + bias;
        hn = __fdividef(1.f, 1.f + __expf(-z));
        hbuf[1][oglob] = hn;
        xp_cur = __ldg(&g_xproj[1 * HID + oglob]);
    }
    __syncthreads();
    if (tid == 0) {
        asm volatile("fence.proxy.async.shared::cta;" ::: "memory");
        uint32_t off = (uint32_t)(1 * HID + (int)rank * KHALF) * 4u;
        bulk_s2s(rh_base + off, h_base + off, HALF_BYTES, rb1);
    }

    uint32_t par0 = 0, par1 = 0;

    for (int t = 1; t < SEQ; t++) {
        const int cur = t & 1;
        const int nxt = cur ^ 1;

        // Prefetch next step's x_proj (one step ahead, hides L2 latency)
        float xp_next = 0.f;
        if (writer && (t + 1 < SEQ))
            xp_next = __ldg(&g_xproj[(t + 1) * HID + oglob]);

        unsigned long long a0 = 0ull, a1 = 0ull;

        // ---- phase A: local half (available since last __syncthreads) ----
        {
            const ulonglong2* h2 =
                reinterpret_cast<const ulonglong2*>(&hbuf[cur][kL0]);
            #pragma unroll
            for (int i = 0; i < KSEG / 4; i++) {
                ulonglong2 hv = h2[i];
                fma2(a0, wl[2 * i],     hv.x);
                fma2(a1, wl[2 * i + 1], hv.y);
            }
        }

        // ---- wait for peer's bulk (remote half), then re-arm for t+2 ----
        if (cur) { mbar_wait(b_addr1, par1); par1 ^= 1; }
        else     { mbar_wait(b_addr0, par0); par0 ^= 1; }
        if (tid == 0) mbar_expect(cur ? b_addr1 : b_addr0, HALF_BYTES);

        // ---- phase B: remote half ----
        {
            const ulonglong2* h2 =
                reinterpret_cast<const ulonglong2*>(&hbuf[cur][kR0]);
            #pragma unroll
            for (int i = 0; i < KSEG / 4; i++) {
                ulonglong2 hv = h2[i];
                fma2(a0, wr[2 * i],     hv.x);
                fma2(a1, wr[2 * i + 1], hv.y);
            }
        }

        // ---- reduce 4 segs via shuffles (lanes seg=0..3 adjacent) ----
        float x0, y0, x1, y1;
        unpack2(a0, x0, y0);
        unpack2(a1, x1, y1);
        float s = (x0 + y0) + (x1 + y1);
        s += __shfl_xor_sync(0xFFFFFFFFu, s, 1);
        s += __shfl_xor_sync(0xFFFFFFFFu, s, 2);

        if (writer) {
            float z = s + bias + xp_cur;
            hn = __fdividef(1.f, 1.f + __expf(-z));
            hbuf[nxt][oglob] = hn;
            xp_cur = xp_next;
        }
        __syncthreads();   // reads of hbuf[cur] done; local hbuf[nxt] published

        if (tid == 0) {
            asm volatile("fence.proxy.async.shared::cta;" ::: "memory");
            uint32_t off = (uint32_t)(nxt * HID + (int)rank * KHALF) * 4u;
            bulk_s2s(rh_base + off, h_base + off, HALF_BYTES, nxt ? rb1 : rb0);
        }
    }

    // h_SEQ was produced at t = SEQ-1; writers hold their own component.
    if (writer) out[oglob] = hn;
}

// ---------------------------------------------------------------------------
// kernel_launch
// ---------------------------------------------------------------------------
extern "C" void kernel_launch(void* const* d_in, const int* in_sizes, int n_in,
                              void* d_out, int out_size)
{
    const int*   tokens    = (const int*)d_in[0];
    const float* embedding = (const float*)d_in[1];
    const float* wx_w      = (const float*)d_in[2];
    const float* wx_b      = (const float*)d_in[3];
    const float* wh_w      = (const float*)d_in[4];
    const float* wh_b      = (const float*)d_in[5];
    float*       out       = (float*)d_out;

    xproj_kernel<<<SEQ / TOK_PER_BLK, 256>>>(tokens, embedding, wx_w, wx_b);
    rnn_kernel<<<NCTA, THREADS2>>>(wh_w, wh_b, out);
}

// round 3
// speedup vs baseline: 2.8980x; 2.8980x over previous
#include <cuda_runtime.h>
#include <cstdint>

#define SEQ 4096
#define HID 256
#define EMB 256

// ---------------------------------------------------------------------------
// Scratch: x_proj[t][j] (4096 x 256 fp32 = 4 MB). Device global (no alloc).
// ---------------------------------------------------------------------------
__device__ float g_xproj[SEQ * HID];

// ---------------------------------------------------------------------------
// Phase 1: x_proj = embedding[tokens] @ wx_w.T + wx_b  (~25us, not the bottleneck)
// ---------------------------------------------------------------------------
#define TOK_PER_BLK 16

__global__ __launch_bounds__(256) void xproj_kernel(
    const int* __restrict__ tokens,
    const float* __restrict__ embedding,
    const float* __restrict__ wx_w,
    const float* __restrict__ wx_b)
{
    __shared__ float emb_sm[TOK_PER_BLK * EMB];
    const int tid = threadIdx.x;
    const int t0  = blockIdx.x * TOK_PER_BLK;

    #pragma unroll
    for (int i = 0; i < TOK_PER_BLK; i++) {
        long tok = (long)tokens[t0 + i];
        emb_sm[i * EMB + tid] = embedding[tok * (long)EMB + tid];
    }
    __syncthreads();

    float acc[TOK_PER_BLK];
    #pragma unroll
    for (int i = 0; i < TOK_PER_BLK; i++) acc[i] = 0.f;

    const float4* wrow = reinterpret_cast<const float4*>(wx_w + tid * EMB);
    #pragma unroll 4
    for (int k4 = 0; k4 < EMB / 4; k4++) {
        float4 w = wrow[k4];
        #pragma unroll
        for (int i = 0; i < TOK_PER_BLK; i++) {
            float4 e = *reinterpret_cast<const float4*>(&emb_sm[i * EMB + 4 * k4]);
            acc[i] += w.x * e.x + w.y * e.y + w.z * e.z + w.w * e.w;
        }
    }

    const float b = wx_b[tid];
    #pragma unroll
    for (int i = 0; i < TOK_PER_BLK; i++)
        g_xproj[(t0 + i) * HID + tid] = acc[i] + b;
}

// ---------------------------------------------------------------------------
// Phase 2: serial recurrence, 2-CTA cluster. NO barrier.cluster / mbarrier /
// bulk-async in the loop — cross-CTA handshake is sentinel-based data polling
// over plain st.shared::cluster.
//
// Thread map (512 thr/CTA): o = tid>>2 (128 outputs/CTA), seg = tid&3.
// Each thread: 32 local k's + 32 remote k's, weights as packed f32x2 in regs
// (64 regs), dot via fma.rn.f32x2, 4-seg reduce via 2 warp shuffles.
//
// h layout (per slot): 4 chunks of 32 floats, chunk stride CH=36 floats
// (16B-aligned, shifts each seg by 4 banks -> conflict-free 8-way broadcast).
//   loc[2][144]    local half   (written by own writers, plain smem)
//   rsrc[2][144]   remote inbox (peer writes via st.shared::cluster;
//                   sentinel -1.0f when empty; sigmoid values are > 0)
//   rstage[2][144] clean copy of remote half for compute
//
// Per step t (cur=t&1, nxt=cur^1):
//   phaseA: local-half FMAs from loc[cur]
//   tid<128: poll rsrc[cur][tid'] until >= 0, copy -> rstage[cur], reset -1
//   __syncthreads()                                      (sync1)
//   phaseB: remote-half FMAs from rstage[cur]
//   shuffle-reduce; writer: sigmoid -> loc[nxt] local + st.shared::cluster
//   to peer rsrc[nxt] (skip on last step)
//   __syncthreads()                                      (sync2)
//
// Slot-reuse safety: our store into peer rsrc[nxt] at end of step t is
// causally AFTER the peer reset rsrc[nxt] (peer reset it pre-sync1 of its
// step t-1; its end-of-(t-1) stores — which our step-t phaseB values depend
// on — are post-sync1). rstage[cur] overwritten only at step t+2, after
// sync boundaries that order it after all step-t reads. Single 4B store
// atomicity makes each value its own ready flag; no fences needed.
// ---------------------------------------------------------------------------
#define NCTA 2
#define THREADS2 512
#define OUT_PER_CTA 128
#define KSEG 32          // k's per thread per half
#define CH 36            // padded chunk stride (floats)
#define HALFP (4 * CH)   // 144 floats per slot
#define SENT -1.0f

__device__ __forceinline__ uint32_t smem_u32(const void* p) {
    uint32_t a;
    asm("{ .reg .u64 t; cvta.to.shared.u64 t, %1; cvt.u32.u64 %0, t; }"
        : "=r"(a) : "l"(p));
    return a;
}
__device__ __forceinline__ uint32_t mapa_peer(uint32_t a, uint32_t rank) {
    uint32_t r;
    asm("mapa.shared::cluster.u32 %0, %1, %2;" : "=r"(r) : "r"(a), "r"(rank));
    return r;
}
__device__ __forceinline__ void st_remote_f32(uint32_t a, float v) {
    asm volatile("st.shared::cluster.f32 [%0], %1;" :: "r"(a), "f"(v) : "memory");
}
__device__ __forceinline__ void fma2(unsigned long long& acc,
                                     unsigned long long a, unsigned long long b) {
    asm("fma.rn.f32x2 %0, %1, %2, %0;" : "+l"(acc) : "l"(a), "l"(b));
}
__device__ __forceinline__ unsigned long long pack2(float x, float y) {
    unsigned long long v;
    asm("mov.b64 %0, {%1, %2};" : "=l"(v) : "f"(x), "f"(y));
    return v;
}
__device__ __forceinline__ void unpack2(unsigned long long v, float& x, float& y) {
    asm("mov.b64 {%0, %1}, %2;" : "=f"(x), "=f"(y) : "l"(v));
}

__global__ __launch_bounds__(THREADS2, 1) __cluster_dims__(NCTA, 1, 1)
void rnn_kernel(const float* __restrict__ wh_w,
                const float* __restrict__ wh_b,
                float* __restrict__ out)
{
    __shared__ __align__(16) float loc[2][HALFP];
    __shared__ __align__(16) float rsrc[2][HALFP];
    __shared__ __align__(16) float rstage[2][HALFP];

    const int tid = threadIdx.x;
    uint32_t rank; asm("mov.u32 %0, %%cluster_ctarank;" : "=r"(rank));
    const uint32_t peer = rank ^ 1u;

    const int o      = tid >> 2;          // output within CTA (0..127)
    const int seg    = tid & 3;           // k-segment (0..3)
    const int oglob  = (int)rank * OUT_PER_CTA + o;
    const bool writer = (seg == 0);

    // Register-resident packed weights: local half then remote half.
    // local k's:  rank*128 + seg*32 + [0..31]
    // remote k's: peer*128 + seg*32 + [0..31]
    unsigned long long wl[KSEG / 2], wr[KSEG / 2];
    {
        const float* rowL = wh_w + oglob * HID + (int)rank * 128 + seg * KSEG;
        const float* rowR = wh_w + oglob * HID + (int)peer * 128 + seg * KSEG;
        #pragma unroll
        for (int i = 0; i < KSEG / 2; i++) {
            wl[i] = pack2(rowL[2 * i], rowL[2 * i + 1]);
            wr[i] = pack2(rowR[2 * i], rowR[2 * i + 1]);
        }
    }

    // Init: h0 = 0 -> loc[0]=0, rstage[0]=0 via rsrc[0]=0 (pollers will copy);
    // rsrc[1] = SENT (armed for peer's first store at end of step 0).
    for (int i = tid; i < HALFP; i += THREADS2) {
        loc[0][i]  = 0.f;
        rsrc[0][i] = 0.f;
        rsrc[1][i] = SENT;
    }

    float bias = 0.f, xp_cur = 0.f, hn = 0.f;
    if (writer) {
        bias   = wh_b[oglob];
        xp_cur = g_xproj[oglob];
    }
    __syncthreads();
    // One-time cluster barrier: both CTAs' sentinel init visible before any
    // remote store. Never executed again.
    asm volatile("barrier.cluster.arrive.aligned;" ::: "memory");
    asm volatile("barrier.cluster.wait.aligned;"   ::: "memory");

    // Remote base of peer's rsrc
    const uint32_t rsrc_peer = mapa_peer(smem_u32(&rsrc[0][0]), peer);
    // writer's padded position for output o (as float index)
    const int wpos = (o >> 5) * CH + (o & 31);

    // poller setup (tid < 128): value index tid -> padded slot
    const int ppos = (tid >> 5) * CH + (tid & 31);

    for (int t = 0; t < SEQ; t++) {
        const int cur = t & 1;
        const int nxt = cur ^ 1;

        // Prefetch next step's x_proj (L2-resident)
        float xp_next = 0.f;
        if (writer && (t + 1 < SEQ))
            xp_next = __ldg(&g_xproj[(t + 1) * HID + oglob]);

        unsigned long long a0 = 0ull, a1 = 0ull;

        // ---- phase A: local half ----
        {
            const ulonglong2* h2 =
                reinterpret_cast<const ulonglong2*>(&loc[cur][seg * CH]);
            #pragma unroll
            for (int i = 0; i < KSEG / 4; i++) {
                ulonglong2 hv = h2[i];
                fma2(a0, wl[2 * i],     hv.x);
                fma2(a1, wl[2 * i + 1], hv.y);
            }
        }

        // ---- poll remote inbox, copy to stage, re-arm sentinel ----
        if (tid < OUT_PER_CTA) {
            volatile float* p = &rsrc[cur][ppos];
            float v = *p;
            while (v < 0.f) v = *p;
            rstage[cur][ppos] = v;
            *p = SENT;
        }
        __syncthreads();   // sync1: rstage[cur] complete, rsrc[cur] re-armed

        // ---- phase B: remote half ----
        {
            const ulonglong2* h2 =
                reinterpret_cast<const ulonglong2*>(&rstage[cur][seg * CH]);
            #pragma unroll
            for (int i = 0; i < KSEG / 4; i++) {
                ulonglong2 hv = h2[i];
                fma2(a0, wr[2 * i],     hv.x);
                fma2(a1, wr[2 * i + 1], hv.y);
            }
        }

        // ---- reduce 4 segs (lanes o*4+seg adjacent) ----
        float x0, y0, x1, y1;
        unpack2(a0, x0, y0);
        unpack2(a1, x1, y1);
        float s = (x0 + y0) + (x1 + y1);
        s += __shfl_xor_sync(0xFFFFFFFFu, s, 1);
        s += __shfl_xor_sync(0xFFFFFFFFu, s, 2);

        if (writer) {
            float z = s + bias + xp_cur;
            hn = __fdividef(1.f, 1.f + __expf(-z));
            loc[nxt][wpos] = hn;                        // local copy
            if (t + 1 < SEQ) {                          // push to peer inbox
                uint32_t addr = rsrc_peer +
                    (uint32_t)(nxt * HALFP + wpos) * 4u;
                st_remote_f32(addr, hn);
            }
            xp_cur = xp_next;
        }
        __syncthreads();   // sync2: loc[nxt] published; reads of [cur] done
    }

    if (writer) out[oglob] = hn;
}

// ---------------------------------------------------------------------------
// kernel_launch
//   d_in: [0] tokens i32[4096], [1] embedding f32[128000*256],
//         [2] wx_w f32[256*256], [3] wx_b f32[256],
//         [4] wh_w f32[256*256], [5] wh_b f32[256]
// ---------------------------------------------------------------------------
extern "C" void kernel_launch(void* const* d_in, const int* in_sizes, int n_in,
                              void* d_out, int out_size)
{
    const int*   tokens    = (const int*)d_in[0];
    const float* embedding = (const float*)d_in[1];
    const float* wx_w      = (const float*)d_in[2];
    const float* wx_b      = (const float*)d_in[3];
    const float* wh_w      = (const float*)d_in[4];
    const float* wh_b      = (const float*)d_in[5];
    float*       out       = (float*)d_out;

    xproj_kernel<<<SEQ / TOK_PER_BLK, 256>>>(tokens, embedding, wx_w, wx_b);
    rnn_kernel<<<NCTA, THREADS2>>>(wh_w, wh_b, out);
}